// round 2
// baseline (speedup 1.0000x reference)
#include <cuda_runtime.h>
#include <math.h>
#include <stdint.h>

#define BSZ 4
#define NX 8192
#define NY 1024
#define KNN 20
#define CD 24
#define HD 128
#define NB 5
#define NROWS (BSZ*NX*KNN)   /* 655360 */
#define NPTS  (BSZ*NX)       /* 32768  */
#define BN_EPS 1e-5f

/* ---------------- scratch (static device arrays: allowed) ---------------- */
__device__ int   g_idx[NROWS];                 /* 2.6 MB */
__device__ float g_U[BSZ*NY*HD];               /* 2 MB   */
__device__ float g_V[BSZ*NX*HD];               /* 16 MB  */
__device__ float g_h2[(size_t)NROWS*HD];       /* 335 MB */
__device__ float g_h3[NROWS*CD];               /* 63 MB  */
__device__ float g_cfeat[NPTS*CD];             /* 3 MB   */
__device__ float g_sum[3*HD];
__device__ float g_sumsq[3*HD];
__device__ float g_scale[3*HD];
__device__ float g_shift[3*HD];

/* ---------------- K0: zero stat accumulators ---------------- */
__global__ void k_zero() {
    int t = threadIdx.x;
    if (t < 3*HD) { g_sum[t] = 0.f; g_sumsq[t] = 0.f; }
}

/* ---------------- K1: KNN (top-20 smallest d2 per query) ---------------- */
__global__ void k_knn(const float* __restrict__ p, const float* __restrict__ pc) {
    __shared__ float qx[NY], qy[NY], qz[NY], qn[NY];
    int b = blockIdx.y;
    int t = threadIdx.x;
    for (int j = t; j < NY; j += blockDim.x) {
        float x = pc[(b*NY + j)*3 + 0];
        float y = pc[(b*NY + j)*3 + 1];
        float z = pc[(b*NY + j)*3 + 2];
        qx[j] = x; qy[j] = y; qz[j] = z;
        qn[j] = x*x + y*y + z*z;
    }
    __syncthreads();

    int n = blockIdx.x * blockDim.x + t;
    float px = p[(b*NX + n)*3 + 0];
    float py = p[(b*NX + n)*3 + 1];
    float pz = p[(b*NX + n)*3 + 2];
    float pn = px*px + py*py + pz*pz;

    float bd[KNN]; int bi[KNN];
#pragma unroll
    for (int s = 0; s < KNN; s++) { bd[s] = 3.4e38f; bi[s] = 0; }
    float worst = 3.4e38f; int wpos = 0;

    for (int j = 0; j < NY; j++) {
        float d = pn + qn[j] - 2.f*(px*qx[j] + py*qy[j] + pz*qz[j]);
        if (d < worst) {
#pragma unroll
            for (int s = 0; s < KNN; s++) if (s == wpos) { bd[s] = d; bi[s] = j; }
            /* rescan for new worst */
            worst = bd[0]; wpos = 0;
#pragma unroll
            for (int s = 1; s < KNN; s++) if (bd[s] > worst) { worst = bd[s]; wpos = s; }
        }
    }
    int base = (b*NX + n)*KNN;
#pragma unroll
    for (int s = 0; s < KNN; s++) g_idx[base + s] = bi[s];
}

/* ---------------- K1b: precompute U = pc@W[0:3] + feat@W[6:30] ---------------- */
__global__ void k_preU(const float* __restrict__ pc, const float* __restrict__ feat,
                       const float* __restrict__ w1) {
    __shared__ float in_s[32][28];
    int base = blockIdx.x * 32;
    int t = threadIdx.x;
    for (int e = t; e < 32*27; e += 128) {
        int r = e / 27, k = e % 27;
        int row = base + r;
        in_s[r][k] = (k < 3) ? pc[row*3 + k] : feat[row*24 + (k - 3)];
    }
    __syncthreads();
    float wr[27];
#pragma unroll
    for (int d = 0; d < 3; d++)  wr[d]     = w1[d*HD + t];
#pragma unroll
    for (int k = 0; k < 24; k++) wr[3 + k] = w1[(6 + k)*HD + t];
    for (int r = 0; r < 32; r++) {
        float acc = 0.f;
#pragma unroll
        for (int k = 0; k < 27; k++) acc = fmaf(in_s[r][k], wr[k], acc);
        g_U[(base + r)*HD + t] = acc;
    }
}

/* ---------------- K1c: precompute V = p@(W[3:6]-W[0:3]) ---------------- */
__global__ void k_preV(const float* __restrict__ p, const float* __restrict__ w1) {
    __shared__ float ps[64][4];
    int base = blockIdx.x * 64;
    int t = threadIdx.x;
    for (int e = t; e < 64*3; e += 128) {
        int r = e / 3, d = e % 3;
        ps[r][d] = p[(base + r)*3 + d];
    }
    __syncthreads();
    float wd0 = w1[3*HD + t] - w1[0*HD + t];
    float wd1 = w1[4*HD + t] - w1[1*HD + t];
    float wd2 = w1[5*HD + t] - w1[2*HD + t];
    for (int r = 0; r < 64; r++) {
        float v = fmaf(ps[r][0], wd0, fmaf(ps[r][1], wd1, ps[r][2]*wd2));
        g_V[(base + r)*HD + t] = v;
    }
}

/* ---------------- K2: stats of h1 = U[j]+V[n] (layer-1 BN) ---------------- */
__global__ void k_stats1() {
    __shared__ int uo[512], vo[512];
    int blk = blockIdx.x, t = threadIdx.x;
    int base = blk * 512;
    for (int r = t; r < 512; r += 256) {
        int grow = base + r;
        int j = g_idx[grow];
        int b = grow / (NX*KNN);
        int n = (grow / KNN) % NX;
        uo[r] = (b*NY + j)*HD;
        vo[r] = (b*NX + n)*HD;
    }
    __syncthreads();
    int c = t & 127, rg = t >> 7;
    float s = 0.f, s2 = 0.f;
    for (int r = rg; r < 512; r += 2) {
        float v = g_U[uo[r] + c] + g_V[vo[r] + c];
        s += v; s2 += v*v;
    }
    atomicAdd(&g_sum[c], s);
    atomicAdd(&g_sumsq[c], s2);
}

/* ---------------- finalize BN layer: scale/shift ---------------- */
__global__ void k_finalize(int L, int C, float invN,
                           const float* __restrict__ g, const float* __restrict__ b) {
    int c = threadIdx.x;
    if (c < C) {
        float mean = g_sum[L*HD + c] * invN;
        float var  = g_sumsq[L*HD + c] * invN - mean*mean;
        float sc = g[c] * rsqrtf(var + BN_EPS);
        g_scale[L*HD + c] = sc;
        g_shift[L*HD + c] = b[c] - mean*sc;
    }
}

/* ---------------- K4: conv2 GEMM (gathers h1 on the fly) + stats2 ----------- */
/* tile: 64 rows x 128 cols, 256 threads, smem A(32K)+W(64K) */
__global__ void __launch_bounds__(256) k_conv2(const float* __restrict__ w2) {
    extern __shared__ char smemraw[];
    float* a_s = (float*)smemraw;              /* 64*128   */
    float* w_s = a_s + 64*128;                 /* 128*128  */
    float* sc  = w_s + 128*128;                /* 128      */
    float* sh  = sc + 128;                     /* 128      */
    int*   uo  = (int*)(sh + 128);             /* 64       */
    int*   vo  = uo + 64;                      /* 64       */

    int t = threadIdx.x, blk = blockIdx.x;
    int rbase = blk * 64;
    if (t < 64) {
        int grow = rbase + t;
        int j = g_idx[grow];
        int b = grow / (NX*KNN);
        int n = (grow / KNN) % NX;
        uo[t] = (b*NY + j)*HD;
        vo[t] = (b*NX + n)*HD;
    }
    if (t < 128) { sc[t] = g_scale[t]; sh[t] = g_shift[t]; }
    for (int e = t; e < 128*128; e += 256) w_s[e] = __ldg(&w2[e]);
    __syncthreads();

    {   /* stage A tile: h1 = U+V, then bn1 + lrelu */
        int k = t & 127, r0 = t >> 7;
        for (int r = r0; r < 64; r += 2) {
            float v = g_U[uo[r] + k] + g_V[vo[r] + k];
            v = fmaf(sc[k], v, sh[k]);
            v = (v > 0.f) ? v : 0.2f*v;
            a_s[r*128 + k] = v;
        }
    }
    __syncthreads();

    int col = t & 127, rg = t >> 7;
    float acc[32];
#pragma unroll
    for (int r = 0; r < 32; r++) acc[r] = 0.f;
    const float* ar = a_s + (rg*32)*128;

    for (int k = 0; k < 128; k += 4) {
        float w0 = w_s[(k+0)*128 + col];
        float w1 = w_s[(k+1)*128 + col];
        float wv2 = w_s[(k+2)*128 + col];
        float w3 = w_s[(k+3)*128 + col];
#pragma unroll
        for (int r = 0; r < 32; r++) {
            float4 av = *(const float4*)&ar[r*128 + k];
            acc[r] = fmaf(av.x, w0, acc[r]);
            acc[r] = fmaf(av.y, w1, acc[r]);
            acc[r] = fmaf(av.z, wv2, acc[r]);
            acc[r] = fmaf(av.w, w3, acc[r]);
        }
    }
    float s = 0.f, s2 = 0.f;
    size_t obase = (size_t)(rbase + rg*32)*HD + col;
#pragma unroll
    for (int r = 0; r < 32; r++) {
        float v = acc[r];
        g_h2[obase + (size_t)r*HD] = v;
        s += v; s2 += v*v;
    }
    atomicAdd(&g_sum[HD + col], s);
    atomicAdd(&g_sumsq[HD + col], s2);
}

/* ---------------- K6: conv3 GEMM (bn2+lrelu on load) + stats3 ---------------- */
/* tile: 128 rows x 24 cols, 192 threads */
__global__ void k_conv3(const float* __restrict__ w3) {
    extern __shared__ char smemraw[];
    float* a_s = (float*)smemraw;          /* 128*129 (padded) */
    float* w_s = a_s + 128*129;            /* 128*24  */
    float* sc  = w_s + 128*24;             /* 128 */
    float* sh  = sc + 128;                 /* 128 */
    float* red = sh + 128;                 /* 48  */

    int t = threadIdx.x, blk = blockIdx.x;
    int rbase = blk * 128;
    for (int e = t; e < 128*24; e += 192) w_s[e] = __ldg(&w3[e]);
    if (t < 128) { sc[t] = g_scale[HD + t]; sh[t] = g_shift[HD + t]; }
    if (t < 48)  red[t] = 0.f;
    __syncthreads();

    for (int e = t; e < 128*128; e += 192) {
        int r = e >> 7, k = e & 127;
        float v = g_h2[(size_t)(rbase + r)*HD + k];
        v = fmaf(sc[k], v, sh[k]);
        v = (v > 0.f) ? v : 0.2f*v;
        a_s[r*129 + k] = v;
    }
    __syncthreads();

    int col = t % 24, rg = t / 24;   /* rg 0..7, rows r*8+rg */
    float acc[16];
#pragma unroll
    for (int r = 0; r < 16; r++) acc[r] = 0.f;
    for (int k = 0; k < 128; k++) {
        float wv = w_s[k*24 + col];
#pragma unroll
        for (int r = 0; r < 16; r++)
            acc[r] = fmaf(a_s[(r*8 + rg)*129 + k], wv, acc[r]);
    }
    float s = 0.f, s2 = 0.f;
#pragma unroll
    for (int r = 0; r < 16; r++) {
        int grow = rbase + r*8 + rg;
        float v = acc[r];
        g_h3[grow*CD + col] = v;
        s += v; s2 += v*v;
    }
    atomicAdd(&red[col], s);
    atomicAdd(&red[24 + col], s2);
    __syncthreads();
    if (t < 24) {
        atomicAdd(&g_sum[2*HD + t], red[t]);
        atomicAdd(&g_sumsq[2*HD + t], red[24 + t]);
    }
}

/* ---------------- K8: k-pool (max/min), bn3 (+sign), lrelu -> c ------------- */
__global__ void k_pool() {
    int g = blockIdx.x * blockDim.x + threadIdx.x;
    if (g >= NPTS*CD) return;
    int pt = g / CD, col = g % CD;
    const float* base = g_h3 + pt*KNN*CD + col;
    float mx = -3.4e38f, mn = 3.4e38f;
#pragma unroll
    for (int kk = 0; kk < KNN; kk++) {
        float v = base[kk*CD];
        mx = fmaxf(mx, v); mn = fminf(mn, v);
    }
    float sc = g_scale[2*HD + col], sh = g_shift[2*HD + col];
    float z = fmaf(sc, (sc >= 0.f ? mx : mn), sh);
    z = (z > 0.f) ? z : 0.2f*z;
    g_cfeat[g] = z;
}

/* ---------------- K9: ResNet-FC head -> occ ---------------- */
/* block = 64 points, 256 threads = 128 cols x 2 rowgroups of 32 rows */
__global__ void __launch_bounds__(256) k_head(const float* __restrict__ p,
                       const float* __restrict__ fpw, const float* __restrict__ fpb,
                       const float* __restrict__ fcw, const float* __restrict__ fcb,
                       const float* __restrict__ b0w, const float* __restrict__ b0b,
                       const float* __restrict__ b1w, const float* __restrict__ b1b,
                       const float* __restrict__ fow, const float* __restrict__ fob,
                       float* __restrict__ out) {
    extern __shared__ char smemraw[];
    float* net  = (float*)smemraw;     /* 64*128 */
    float* rnet = net  + 64*128;       /* 64*128 */
    float* rhh  = rnet + 64*128;       /* 64*128 */
    float* cb   = rhh  + 64*128;       /* 64*24  */
    float* pb   = cb   + 64*24;        /* 192    */
    float* fo   = pb   + 192;          /* 128    */

    int t = threadIdx.x;
    int base = blockIdx.x * 64;
    for (int e = t; e < 64*CD; e += 256) cb[e] = g_cfeat[base*CD + e];
    if (t < 192) pb[t] = p[base*3 + t];
    if (t < 128) fo[t] = fow[t];
    __syncthreads();

    int col = t & 127, rg = t >> 7;

    { /* net = p @ fc_p_w + b */
        float w0 = fpw[col], w1 = fpw[HD + col], w2 = fpw[2*HD + col];
        float bb = fpb[col];
        for (int r = rg; r < 64; r += 2) {
            float v = bb;
            v = fmaf(pb[r*3 + 0], w0, v);
            v = fmaf(pb[r*3 + 1], w1, v);
            v = fmaf(pb[r*3 + 2], w2, v);
            net[r*128 + col] = v;
        }
    }
    __syncthreads();

    for (int i = 0; i < NB; i++) {
        { /* net += c @ fc_c[i] + b ; rnet = relu(net) */
            float wk[CD];
#pragma unroll
            for (int k = 0; k < CD; k++) wk[k] = __ldg(&fcw[(i*CD + k)*HD + col]);
            float bb = fcb[i*HD + col];
            for (int r = rg; r < 64; r += 2) {
                float v = net[r*128 + col] + bb;
#pragma unroll
                for (int k = 0; k < CD; k++) v = fmaf(cb[r*CD + k], wk[k], v);
                net[r*128 + col]  = v;
                rnet[r*128 + col] = fmaxf(v, 0.f);
            }
        }
        __syncthreads();
        { /* rhh = relu( rnet @ blk0[i] + b ) */
            float acc[32];
            float bb = b0b[i*HD + col];
#pragma unroll
            for (int r = 0; r < 32; r++) acc[r] = bb;
            const float* wbase = b0w + (size_t)i*HD*HD;
#pragma unroll 4
            for (int k = 0; k < HD; k++) {
                float wv = __ldg(&wbase[k*HD + col]);
#pragma unroll
                for (int r = 0; r < 32; r++)
                    acc[r] = fmaf(rnet[(2*r + rg)*128 + k], wv, acc[r]);
            }
#pragma unroll
            for (int r = 0; r < 32; r++)
                rhh[(2*r + rg)*128 + col] = fmaxf(acc[r], 0.f);
        }
        __syncthreads();
        { /* net += rhh @ blk1[i] + b */
            float acc[32];
            float bb = b1b[i*HD + col];
#pragma unroll
            for (int r = 0; r < 32; r++) acc[r] = bb;
            const float* wbase = b1w + (size_t)i*HD*HD;
#pragma unroll 4
            for (int k = 0; k < HD; k++) {
                float wv = __ldg(&wbase[k*HD + col]);
#pragma unroll
                for (int r = 0; r < 32; r++)
                    acc[r] = fmaf(rhh[(2*r + rg)*128 + k], wv, acc[r]);
            }
#pragma unroll
            for (int r = 0; r < 32; r++)
                net[(2*r + rg)*128 + col] += acc[r];
        }
        __syncthreads();
    }

    if (t < 64) {
        float s = fob[0];
        for (int c2 = 0; c2 < HD; c2++)
            s = fmaf(fmaxf(net[t*128 + c2], 0.f), fo[c2], s);
        out[base + t] = s;
    }
}

/* ---------------- launch ---------------- */
extern "C" void kernel_launch(void* const* d_in, const int* in_sizes, int n_in,
                              void* d_out, int out_size) {
    (void)in_sizes; (void)n_in; (void)out_size;
    const float* p     = (const float*)d_in[0];
    const float* pc    = (const float*)d_in[1];
    const float* feat  = (const float*)d_in[2];
    const float* w1    = (const float*)d_in[3];
    const float* bn1g  = (const float*)d_in[4];
    const float* bn1b  = (const float*)d_in[5];
    const float* w2    = (const float*)d_in[6];
    const float* bn2g  = (const float*)d_in[7];
    const float* bn2b  = (const float*)d_in[8];
    const float* w3    = (const float*)d_in[9];
    const float* bn3g  = (const float*)d_in[10];
    const float* bn3b  = (const float*)d_in[11];
    const float* fpw   = (const float*)d_in[12];
    const float* fpb   = (const float*)d_in[13];
    const float* fcw   = (const float*)d_in[14];
    const float* fcb   = (const float*)d_in[15];
    const float* b0w   = (const float*)d_in[16];
    const float* b0b   = (const float*)d_in[17];
    const float* b1w   = (const float*)d_in[18];
    const float* b1b   = (const float*)d_in[19];
    const float* fow   = (const float*)d_in[20];
    const float* fob   = (const float*)d_in[21];
    float* out = (float*)d_out;

    const int SMEM2 = (64*128 + 128*128 + 256) * 4 + 128 * 4;      /* ~99.8 KB */
    const int SMEM3 = (128*129 + 128*24 + 256 + 48) * 4;           /* ~79.5 KB */
    const int SMEMH = (3*64*128 + 64*24 + 192 + 128) * 4;          /* ~105.7 KB */
    cudaFuncSetAttribute(k_conv2, cudaFuncAttributeMaxDynamicSharedMemorySize, SMEM2);
    cudaFuncSetAttribute(k_conv3, cudaFuncAttributeMaxDynamicSharedMemorySize, SMEM3);
    cudaFuncSetAttribute(k_head,  cudaFuncAttributeMaxDynamicSharedMemorySize, SMEMH);

    float invN = 1.0f / (float)NROWS;

    k_zero<<<1, 384>>>();
    k_knn<<<dim3(NX/256, BSZ), 256>>>(p, pc);
    k_preU<<<(BSZ*NY)/32, 128>>>(pc, feat, w1);
    k_preV<<<NPTS/64, 128>>>(p, w1);
    k_stats1<<<NROWS/512, 256>>>();
    k_finalize<<<1, 128>>>(0, 128, invN, bn1g, bn1b);
    k_conv2<<<NROWS/64, 256, SMEM2>>>(w2);
    k_finalize<<<1, 128>>>(1, 128, invN, bn2g, bn2b);
    k_conv3<<<NROWS/128, 192, SMEM3>>>(w3);
    k_finalize<<<1, 128>>>(2, 24, invN, bn3g, bn3b);
    k_pool<<<(NPTS*CD)/256, 256>>>();
    k_head<<<NPTS/64, 256, SMEMH>>>(p, fpw, fpb, fcw, fcb,
                                    b0w, b0b, b1w, b1b, fow, fob, out);
}

// round 3
// speedup vs baseline: 1.1017x; 1.1017x over previous
#include <cuda_runtime.h>
#include <cuda_fp16.h>
#include <math.h>
#include <stdint.h>

#define BSZ 4
#define NX 8192
#define NY 1024
#define KNN 20
#define CD 24
#define HD 128
#define NB 5
#define NROWS (BSZ*NX*KNN)   /* 655360 */
#define NPTS  (BSZ*NX)       /* 32768  */
#define BN_EPS 1e-5f

/* ---------------- scratch ---------------- */
__device__ int    g_idx[NROWS];                 /* 2.6 MB */
__device__ float  g_U[BSZ*NY*HD];               /* 2 MB   */
__device__ float  g_V[BSZ*NX*HD];               /* 16 MB  */
__device__ __half g_h2h[(size_t)NROWS*HD];      /* 168 MB */
__device__ float  g_pmax[NPTS*CD];              /* 3 MB   */
__device__ float  g_pmin[NPTS*CD];              /* 3 MB   */
__device__ float  g_sum[3*HD];
__device__ float  g_sumsq[3*HD];
__device__ float  g_scale[3*HD];
__device__ float  g_shift[3*HD];

/* ---------------- K0: zero stat accumulators ---------------- */
__global__ void k_zero() {
    int t = threadIdx.x;
    if (t < 3*HD) { g_sum[t] = 0.f; g_sumsq[t] = 0.f; }
}

/* ---------------- K1: KNN ---------------- */
__global__ void k_knn(const float* __restrict__ p, const float* __restrict__ pc) {
    __shared__ float qx[NY], qy[NY], qz[NY], qn[NY];
    int b = blockIdx.y;
    int t = threadIdx.x;
    for (int j = t; j < NY; j += blockDim.x) {
        float x = pc[(b*NY + j)*3 + 0];
        float y = pc[(b*NY + j)*3 + 1];
        float z = pc[(b*NY + j)*3 + 2];
        qx[j] = x; qy[j] = y; qz[j] = z;
        qn[j] = x*x + y*y + z*z;
    }
    __syncthreads();

    int n = blockIdx.x * blockDim.x + t;
    float px = p[(b*NX + n)*3 + 0];
    float py = p[(b*NX + n)*3 + 1];
    float pz = p[(b*NX + n)*3 + 2];
    float pn = px*px + py*py + pz*pz;

    float bd[KNN]; int bi[KNN];
#pragma unroll
    for (int s = 0; s < KNN; s++) { bd[s] = 3.4e38f; bi[s] = 0; }
    float worst = 3.4e38f; int wpos = 0;

    for (int j = 0; j < NY; j++) {
        float d = pn + qn[j] - 2.f*(px*qx[j] + py*qy[j] + pz*qz[j]);
        if (d < worst) {
#pragma unroll
            for (int s = 0; s < KNN; s++) if (s == wpos) { bd[s] = d; bi[s] = j; }
            worst = bd[0]; wpos = 0;
#pragma unroll
            for (int s = 1; s < KNN; s++) if (bd[s] > worst) { worst = bd[s]; wpos = s; }
        }
    }
    int base = (b*NX + n)*KNN;
#pragma unroll
    for (int s = 0; s < KNN; s++) g_idx[base + s] = bi[s];
}

/* ---------------- K1b: U = pc@W[0:3] + feat@W[6:30] ---------------- */
__global__ void k_preU(const float* __restrict__ pc, const float* __restrict__ feat,
                       const float* __restrict__ w1) {
    __shared__ float in_s[32][28];
    int base = blockIdx.x * 32;
    int t = threadIdx.x;
    for (int e = t; e < 32*27; e += 128) {
        int r = e / 27, k = e % 27;
        int row = base + r;
        in_s[r][k] = (k < 3) ? pc[row*3 + k] : feat[row*24 + (k - 3)];
    }
    __syncthreads();
    float wr[27];
#pragma unroll
    for (int d = 0; d < 3; d++)  wr[d]     = w1[d*HD + t];
#pragma unroll
    for (int k = 0; k < 24; k++) wr[3 + k] = w1[(6 + k)*HD + t];
    for (int r = 0; r < 32; r++) {
        float acc = 0.f;
#pragma unroll
        for (int k = 0; k < 27; k++) acc = fmaf(in_s[r][k], wr[k], acc);
        g_U[(base + r)*HD + t] = acc;
    }
}

/* ---------------- K1c: V = p@(W[3:6]-W[0:3]) ---------------- */
__global__ void k_preV(const float* __restrict__ p, const float* __restrict__ w1) {
    __shared__ float ps[64][4];
    int base = blockIdx.x * 64;
    int t = threadIdx.x;
    for (int e = t; e < 64*3; e += 128) {
        int r = e / 3, d = e % 3;
        ps[r][d] = p[(base + r)*3 + d];
    }
    __syncthreads();
    float wd0 = w1[3*HD + t] - w1[0*HD + t];
    float wd1 = w1[4*HD + t] - w1[1*HD + t];
    float wd2 = w1[5*HD + t] - w1[2*HD + t];
    for (int r = 0; r < 64; r++) {
        float v = fmaf(ps[r][0], wd0, fmaf(ps[r][1], wd1, ps[r][2]*wd2));
        g_V[(base + r)*HD + t] = v;
    }
}

/* ---------------- K2: stats of h1 ---------------- */
__global__ void k_stats1() {
    __shared__ int uo[512], vo[512];
    int blk = blockIdx.x, t = threadIdx.x;
    int base = blk * 512;
    for (int r = t; r < 512; r += 256) {
        int grow = base + r;
        int j = g_idx[grow];
        int b = grow / (NX*KNN);
        int n = (grow / KNN) % NX;
        uo[r] = (b*NY + j)*HD;
        vo[r] = (b*NX + n)*HD;
    }
    __syncthreads();
    int c = t & 127, rg = t >> 7;
    float s = 0.f, s2 = 0.f;
    for (int r = rg; r < 512; r += 2) {
        float v = g_U[uo[r] + c] + g_V[vo[r] + c];
        s += v; s2 += v*v;
    }
    atomicAdd(&g_sum[c], s);
    atomicAdd(&g_sumsq[c], s2);
}

/* ---------------- finalize BN ---------------- */
__global__ void k_finalize(int L, int C, float invN,
                           const float* __restrict__ g, const float* __restrict__ b) {
    int c = threadIdx.x;
    if (c < C) {
        float mean = g_sum[L*HD + c] * invN;
        float var  = g_sumsq[L*HD + c] * invN - mean*mean;
        float sc = g[c] * rsqrtf(var + BN_EPS);
        g_scale[L*HD + c] = sc;
        g_shift[L*HD + c] = b[c] - mean*sc;
    }
}

/* ---------------- K4: conv2 GEMM + stats2 (fp16 h2 out) ----------- */
__global__ void __launch_bounds__(256) k_conv2(const float* __restrict__ w2) {
    extern __shared__ char smemraw[];
    float* a_s = (float*)smemraw;              /* 64*128   */
    float* w_s = a_s + 64*128;                 /* 128*128  */
    float* sc  = w_s + 128*128;                /* 128      */
    float* sh  = sc + 128;                     /* 128      */
    int*   uo  = (int*)(sh + 128);             /* 64       */
    int*   vo  = uo + 64;                      /* 64       */

    int t = threadIdx.x, blk = blockIdx.x;
    int rbase = blk * 64;
    if (t < 64) {
        int grow = rbase + t;
        int j = g_idx[grow];
        int b = grow / (NX*KNN);
        int n = (grow / KNN) % NX;
        uo[t] = (b*NY + j)*HD;
        vo[t] = (b*NX + n)*HD;
    }
    if (t < 128) { sc[t] = g_scale[t]; sh[t] = g_shift[t]; }
    for (int e = t; e < 128*128; e += 256) w_s[e] = __ldg(&w2[e]);
    __syncthreads();

    {   /* stage A tile: h1 = U+V, then bn1 + lrelu */
        int k = t & 127, r0 = t >> 7;
        for (int r = r0; r < 64; r += 2) {
            float v = g_U[uo[r] + k] + g_V[vo[r] + k];
            v = fmaf(sc[k], v, sh[k]);
            v = (v > 0.f) ? v : 0.2f*v;
            a_s[r*128 + k] = v;
        }
    }
    __syncthreads();

    int col = t & 127, rg = t >> 7;
    float acc[32];
#pragma unroll
    for (int r = 0; r < 32; r++) acc[r] = 0.f;
    const float* ar = a_s + (rg*32)*128;

    for (int k = 0; k < 128; k += 4) {
        float w0 = w_s[(k+0)*128 + col];
        float w1 = w_s[(k+1)*128 + col];
        float wv2 = w_s[(k+2)*128 + col];
        float w3 = w_s[(k+3)*128 + col];
#pragma unroll
        for (int r = 0; r < 32; r++) {
            float4 av = *(const float4*)&ar[r*128 + k];
            acc[r] = fmaf(av.x, w0, acc[r]);
            acc[r] = fmaf(av.y, w1, acc[r]);
            acc[r] = fmaf(av.z, wv2, acc[r]);
            acc[r] = fmaf(av.w, w3, acc[r]);
        }
    }
    float s = 0.f, s2 = 0.f;
    size_t obase = (size_t)(rbase + rg*32)*HD + col;
#pragma unroll
    for (int r = 0; r < 32; r++) {
        float v = acc[r];
        g_h2h[obase + (size_t)r*HD] = __float2half(v);
        s += v; s2 += v*v;
    }
    atomicAdd(&g_sum[HD + col], s);
    atomicAdd(&g_sumsq[HD + col], s2);
}

/* ---------------- K6: conv3 GEMM (bn2+lrelu on load) + stats3 + fused pool --- */
/* tile: 160 rows = exactly 8 points, 24 cols, 192 threads */
__global__ void __launch_bounds__(192) k_conv3p(const float* __restrict__ w3) {
    extern __shared__ char smemraw[];
    float* a_s = (float*)smemraw;          /* 160*129 (padded) */
    float* w_s = a_s + 160*129;            /* 128*24  */
    float* sc  = w_s + 128*24;             /* 128 */
    float* sh  = sc + 128;                 /* 128 */
    float* red = sh + 128;                 /* 48  */

    int t = threadIdx.x, blk = blockIdx.x;
    int rbase = blk * 160;
    for (int e = t; e < 128*24; e += 192) w_s[e] = __ldg(&w3[e]);
    if (t < 128) { sc[t] = g_scale[HD + t]; sh[t] = g_shift[HD + t]; }
    if (t < 48)  red[t] = 0.f;
    __syncthreads();

    const __half2* hp = (const __half2*)g_h2h + (size_t)rbase*64;
    for (int e = t; e < 160*64; e += 192) {
        int r = e >> 6, kp = e & 63;
        float2 f = __half22float2(hp[(size_t)r*64 + kp]);
        int k0 = 2*kp;
        float v0 = fmaf(sc[k0],   f.x, sh[k0]);   v0 = (v0 > 0.f) ? v0 : 0.2f*v0;
        float v1 = fmaf(sc[k0+1], f.y, sh[k0+1]); v1 = (v1 > 0.f) ? v1 : 0.2f*v1;
        a_s[r*129 + k0]     = v0;
        a_s[r*129 + k0 + 1] = v1;
    }
    __syncthreads();

    int col = t % 24, rg = t / 24;   /* rg 0..7, rows r8*8+rg */
    float acc[20];
#pragma unroll
    for (int r = 0; r < 20; r++) acc[r] = 0.f;
#pragma unroll 4
    for (int k = 0; k < 128; k++) {
        float wv = w_s[k*24 + col];
#pragma unroll
        for (int r = 0; r < 20; r++)
            acc[r] = fmaf(a_s[(r*8 + rg)*129 + k], wv, acc[r]);
    }
    __syncthreads();                 /* a_s now reusable */
    float* h3s = a_s;                /* 160*24 */
    float s = 0.f, s2 = 0.f;
#pragma unroll
    for (int r = 0; r < 20; r++) {
        float v = acc[r];
        h3s[(r*8 + rg)*24 + col] = v;
        s += v; s2 += v*v;
    }
    atomicAdd(&red[col], s);
    atomicAdd(&red[24 + col], s2);
    __syncthreads();

    {   /* fused pool: 8 points x 24 cols == 192 threads */
        int pl = t / 24, c2 = t % 24;
        float mx = -3.4e38f, mn = 3.4e38f;
#pragma unroll
        for (int kk = 0; kk < KNN; kk++) {
            float v = h3s[(pl*KNN + kk)*24 + c2];
            mx = fmaxf(mx, v); mn = fminf(mn, v);
        }
        int pt = blk*8 + pl;
        g_pmax[pt*24 + c2] = mx;
        g_pmin[pt*24 + c2] = mn;
    }
    if (t < 24) {
        atomicAdd(&g_sum[2*HD + t],   red[t]);
        atomicAdd(&g_sumsq[2*HD + t], red[24 + t]);
    }
}

/* ---------------- K9: ResNet-FC head (bn3+pool-select fused on load) -------- */
/* block = 64 points, 256 threads = 32 colgroups(x4) x 8 rowgroups(x8) */
__global__ void __launch_bounds__(256) k_head(const float* __restrict__ p,
                       const float* __restrict__ fpw, const float* __restrict__ fpb,
                       const float* __restrict__ fcw, const float* __restrict__ fcb,
                       const float* __restrict__ b0w, const float* __restrict__ b0b,
                       const float* __restrict__ b1w, const float* __restrict__ b1b,
                       const float* __restrict__ fow, const float* __restrict__ fob,
                       float* __restrict__ out) {
    extern __shared__ char smemraw[];
    float* net  = (float*)smemraw;     /* 64*128 */
    float* rnet = net  + 64*128;       /* 64*128 */
    float* rhh  = rnet + 64*128;       /* 64*128 */
    float* cb   = rhh  + 64*128;       /* 64*24  */
    float* pb   = cb   + 64*24;        /* 192    */
    float* fo   = pb   + 192;          /* 128    */

    int t = threadIdx.x;
    int base = blockIdx.x * 64;
    for (int e = t; e < 64*CD; e += 256) {
        int c2 = e % 24;
        float scv = g_scale[2*HD + c2], shv = g_shift[2*HD + c2];
        float v = (scv >= 0.f) ? g_pmax[base*24 + e] : g_pmin[base*24 + e];
        v = fmaf(scv, v, shv);
        cb[e] = (v > 0.f) ? v : 0.2f*v;
    }
    if (t < 192) pb[t] = p[base*3 + t];
    if (t < 128) fo[t] = fow[t];
    __syncthreads();

    int cg  = (t & 31) * 4;     /* col start: 0,4,...,124 */
    int row0 = (t >> 5) * 8;    /* row start: 0,8,...,56  */

    { /* net = p @ fc_p_w + b */
        float4 w0 = *(const float4*)&fpw[0*HD + cg];
        float4 w1 = *(const float4*)&fpw[1*HD + cg];
        float4 w2 = *(const float4*)&fpw[2*HD + cg];
        float4 b4 = *(const float4*)&fpb[cg];
#pragma unroll
        for (int rr = 0; rr < 8; rr++) {
            int row = row0 + rr;
            float p0 = pb[row*3+0], p1 = pb[row*3+1], p2 = pb[row*3+2];
            float4 v;
            v.x = fmaf(p0,w0.x, fmaf(p1,w1.x, fmaf(p2,w2.x, b4.x)));
            v.y = fmaf(p0,w0.y, fmaf(p1,w1.y, fmaf(p2,w2.y, b4.y)));
            v.z = fmaf(p0,w0.z, fmaf(p1,w1.z, fmaf(p2,w2.z, b4.z)));
            v.w = fmaf(p0,w0.w, fmaf(p1,w1.w, fmaf(p2,w2.w, b4.w)));
            *(float4*)&net[row*128 + cg] = v;
        }
    }
    __syncthreads();

    for (int i = 0; i < NB; i++) {
        { /* net += c @ fc_c[i] + b ; rnet = relu(net) */
            float4 b4 = *(const float4*)&fcb[i*HD + cg];
            float4 acc[8];
#pragma unroll
            for (int rr = 0; rr < 8; rr++) {
                float4 v = *(const float4*)&net[(row0+rr)*128 + cg];
                acc[rr].x = v.x + b4.x; acc[rr].y = v.y + b4.y;
                acc[rr].z = v.z + b4.z; acc[rr].w = v.w + b4.w;
            }
#pragma unroll 4
            for (int k = 0; k < CD; k++) {
                float4 w4 = __ldg((const float4*)&fcw[(i*CD + k)*HD + cg]);
#pragma unroll
                for (int rr = 0; rr < 8; rr++) {
                    float a = cb[(row0+rr)*24 + k];
                    acc[rr].x = fmaf(a, w4.x, acc[rr].x);
                    acc[rr].y = fmaf(a, w4.y, acc[rr].y);
                    acc[rr].z = fmaf(a, w4.z, acc[rr].z);
                    acc[rr].w = fmaf(a, w4.w, acc[rr].w);
                }
            }
#pragma unroll
            for (int rr = 0; rr < 8; rr++) {
                int row = row0 + rr;
                *(float4*)&net[row*128 + cg] = acc[rr];
                float4 rv;
                rv.x = fmaxf(acc[rr].x, 0.f); rv.y = fmaxf(acc[rr].y, 0.f);
                rv.z = fmaxf(acc[rr].z, 0.f); rv.w = fmaxf(acc[rr].w, 0.f);
                *(float4*)&rnet[row*128 + cg] = rv;
            }
        }
        __syncthreads();
        { /* rhh = relu( rnet @ blk0[i] + b ) */
            float4 b4 = *(const float4*)&b0b[i*HD + cg];
            float4 acc[8];
#pragma unroll
            for (int rr = 0; rr < 8; rr++) acc[rr] = b4;
            const float* wbase = b0w + (size_t)i*HD*HD;
#pragma unroll 4
            for (int k = 0; k < HD; k++) {
                float4 w4 = __ldg((const float4*)&wbase[k*HD + cg]);
#pragma unroll
                for (int rr = 0; rr < 8; rr++) {
                    float a = rnet[(row0+rr)*128 + k];
                    acc[rr].x = fmaf(a, w4.x, acc[rr].x);
                    acc[rr].y = fmaf(a, w4.y, acc[rr].y);
                    acc[rr].z = fmaf(a, w4.z, acc[rr].z);
                    acc[rr].w = fmaf(a, w4.w, acc[rr].w);
                }
            }
#pragma unroll
            for (int rr = 0; rr < 8; rr++) {
                float4 rv;
                rv.x = fmaxf(acc[rr].x, 0.f); rv.y = fmaxf(acc[rr].y, 0.f);
                rv.z = fmaxf(acc[rr].z, 0.f); rv.w = fmaxf(acc[rr].w, 0.f);
                *(float4*)&rhh[(row0+rr)*128 + cg] = rv;
            }
        }
        __syncthreads();
        { /* net += rhh @ blk1[i] + b */
            float4 b4 = *(const float4*)&b1b[i*HD + cg];
            float4 acc[8];
#pragma unroll
            for (int rr = 0; rr < 8; rr++) acc[rr] = b4;
            const float* wbase = b1w + (size_t)i*HD*HD;
#pragma unroll 4
            for (int k = 0; k < HD; k++) {
                float4 w4 = __ldg((const float4*)&wbase[k*HD + cg]);
#pragma unroll
                for (int rr = 0; rr < 8; rr++) {
                    float a = rhh[(row0+rr)*128 + k];
                    acc[rr].x = fmaf(a, w4.x, acc[rr].x);
                    acc[rr].y = fmaf(a, w4.y, acc[rr].y);
                    acc[rr].z = fmaf(a, w4.z, acc[rr].z);
                    acc[rr].w = fmaf(a, w4.w, acc[rr].w);
                }
            }
#pragma unroll
            for (int rr = 0; rr < 8; rr++) {
                int row = row0 + rr;
                float4 v = *(const float4*)&net[row*128 + cg];
                v.x += acc[rr].x; v.y += acc[rr].y;
                v.z += acc[rr].z; v.w += acc[rr].w;
                *(float4*)&net[row*128 + cg] = v;
            }
        }
        __syncthreads();
    }

    if (t < 64) {
        float s = fob[0];
        for (int c2 = 0; c2 < HD; c2++)
            s = fmaf(fmaxf(net[t*128 + c2], 0.f), fo[c2], s);
        out[base + t] = s;
    }
}

/* ---------------- launch ---------------- */
extern "C" void kernel_launch(void* const* d_in, const int* in_sizes, int n_in,
                              void* d_out, int out_size) {
    (void)in_sizes; (void)n_in; (void)out_size;
    const float* p     = (const float*)d_in[0];
    const float* pc    = (const float*)d_in[1];
    const float* feat  = (const float*)d_in[2];
    const float* w1    = (const float*)d_in[3];
    const float* bn1g  = (const float*)d_in[4];
    const float* bn1b  = (const float*)d_in[5];
    const float* w2    = (const float*)d_in[6];
    const float* bn2g  = (const float*)d_in[7];
    const float* bn2b  = (const float*)d_in[8];
    const float* w3    = (const float*)d_in[9];
    const float* bn3g  = (const float*)d_in[10];
    const float* bn3b  = (const float*)d_in[11];
    const float* fpw   = (const float*)d_in[12];
    const float* fpb   = (const float*)d_in[13];
    const float* fcw   = (const float*)d_in[14];
    const float* fcb   = (const float*)d_in[15];
    const float* b0w   = (const float*)d_in[16];
    const float* b0b   = (const float*)d_in[17];
    const float* b1w   = (const float*)d_in[18];
    const float* b1b   = (const float*)d_in[19];
    const float* fow   = (const float*)d_in[20];
    const float* fob   = (const float*)d_in[21];
    float* out = (float*)d_out;

    const int SMEM2 = (64*128 + 128*128 + 256) * 4 + 128 * 4;        /* ~99.8 KB */
    const int SMEM3 = (160*129 + 128*24 + 256 + 48) * 4;             /* ~96 KB   */
    const int SMEMH = (3*64*128 + 64*24 + 192 + 128) * 4;            /* ~105.7 KB*/
    cudaFuncSetAttribute(k_conv2,  cudaFuncAttributeMaxDynamicSharedMemorySize, SMEM2);
    cudaFuncSetAttribute(k_conv3p, cudaFuncAttributeMaxDynamicSharedMemorySize, SMEM3);
    cudaFuncSetAttribute(k_head,   cudaFuncAttributeMaxDynamicSharedMemorySize, SMEMH);

    float invN = 1.0f / (float)NROWS;

    k_zero<<<1, 384>>>();
    k_knn<<<dim3(NX/256, BSZ), 256>>>(p, pc);
    k_preU<<<(BSZ*NY)/32, 128>>>(pc, feat, w1);
    k_preV<<<NPTS/64, 128>>>(p, w1);
    k_stats1<<<NROWS/512, 256>>>();
    k_finalize<<<1, 128>>>(0, 128, invN, bn1g, bn1b);
    k_conv2<<<NROWS/64, 256, SMEM2>>>(w2);
    k_finalize<<<1, 128>>>(1, 128, invN, bn2g, bn2b);
    k_conv3p<<<NROWS/160, 192, SMEM3>>>(w3);
    k_finalize<<<1, 128>>>(2, 24, invN, bn3g, bn3b);
    k_head<<<NPTS/64, 256, SMEMH>>>(p, fpw, fpb, fcw, fcb,
                                    b0w, b0b, b1w, b1b, fow, fob, out);
}